// round 4
// baseline (speedup 1.0000x reference)
#include <cuda_runtime.h>
#include <cstddef>

#define BATCH 16384
#define H     128
#define NC    10
#define NATT  3
#define ROWS  128        // rows per block tile
#define TB    256        // threads per block
#define LD    132        // padded smem row stride (floats)
#define KTERMS 11        // Taylor terms k = 0..10
#define EPS   1e-5f

// smem layout (floats):
//  hS  [ROWS*LD]   current hidden state tile
//  uS  [ROWS*LD]   u = tanh(...) tile (also reused for x staging and y temp)
//  wS  [H*H]       current weight matrix
//  vS  [H]         bias
//  gS  [H]         gamma
//  btS [H]         beta
//  wcS [H*NC]      classifier weights
//  bcS [16]        classifier bias (padded)
#define SMEM_FLOATS (2*ROWS*LD + H*H + 3*H + H*NC + 16)
#define SMEM_BYTES  (SMEM_FLOATS * 4)

template<bool TANH>
__device__ __forceinline__ void gemm128(const float* __restrict__ A,
                                        const float* __restrict__ Wm,
                                        const float* __restrict__ bias,
                                        float* __restrict__ D, int tid)
{
    const int tx = tid & 15, ty = tid >> 4;
    const int r0 = ty * 8, c0 = tx * 8;
    float acc[8][8];
    #pragma unroll
    for (int i = 0; i < 8; i++)
        #pragma unroll
        for (int j = 0; j < 8; j++) acc[i][j] = 0.f;

    #pragma unroll 2
    for (int kk = 0; kk < H; kk += 4) {
        float4 aV[8];
        #pragma unroll
        for (int i = 0; i < 8; i++)
            aV[i] = *reinterpret_cast<const float4*>(&A[(r0 + i) * LD + kk]);
        #pragma unroll
        for (int dk = 0; dk < 4; dk++) {
            const float4 b0 = *reinterpret_cast<const float4*>(&Wm[(kk + dk) * H + c0]);
            const float4 b1 = *reinterpret_cast<const float4*>(&Wm[(kk + dk) * H + c0 + 4]);
            const float bb[8] = {b0.x, b0.y, b0.z, b0.w, b1.x, b1.y, b1.z, b1.w};
            #pragma unroll
            for (int i = 0; i < 8; i++) {
                const float a = reinterpret_cast<const float*>(&aV[i])[dk];
                #pragma unroll
                for (int j = 0; j < 8; j++)
                    acc[i][j] = fmaf(a, bb[j], acc[i][j]);
            }
        }
    }

    // epilogue: + bias, optional tanh, store to D (padded, vectorized)
    #pragma unroll
    for (int i = 0; i < 8; i++) {
        float t[8];
        #pragma unroll
        for (int j = 0; j < 8; j++) {
            float v = acc[i][j] + bias[c0 + j];
            t[j] = TANH ? tanhf(v) : v;
        }
        *reinterpret_cast<float4*>(&D[(r0 + i) * LD + c0])     = make_float4(t[0], t[1], t[2], t[3]);
        *reinterpret_cast<float4*>(&D[(r0 + i) * LD + c0 + 4]) = make_float4(t[4], t[5], t[6], t[7]);
    }
}

__global__ __launch_bounds__(TB, 1)
void fused_attn_kernel(const float* __restrict__ x,
                       const float* __restrict__ W_in,
                       const float* __restrict__ b_in,
                       const float* __restrict__ W_att,
                       const float* __restrict__ b_att,
                       const float* __restrict__ gamma,
                       const float* __restrict__ beta,
                       const float* __restrict__ W_c,
                       const float* __restrict__ b_c,
                       float* __restrict__ out)
{
    extern __shared__ float sm[];
    float* hS  = sm;
    float* uS  = hS + ROWS * LD;
    float* wS  = uS + ROWS * LD;
    float* vS  = wS + H * H;
    float* gS  = vS + H;
    float* btS = gS + H;
    float* wcS = btS + H;
    float* bcS = wcS + H * NC;

    const int tid  = threadIdx.x;
    const int row0 = blockIdx.x * ROWS;

    // ---- stage x tile into uS, W_in into wS, vectors ----
    for (int it = tid; it < ROWS * (H / 4); it += TB) {
        const int r  = it >> 5;      // H/4 == 32
        const int c4 = it & 31;
        float4 v = reinterpret_cast<const float4*>(x)[(size_t)(row0 + r) * (H / 4) + c4];
        *reinterpret_cast<float4*>(&uS[r * LD + c4 * 4]) = v;
    }
    for (int it = tid; it < H * H / 4; it += TB) {
        float4 v = reinterpret_cast<const float4*>(W_in)[it];
        *reinterpret_cast<float4*>(&wS[it * 4]) = v;
    }
    for (int it = tid; it < H * NC; it += TB) wcS[it] = W_c[it];
    if (tid < H)  vS[tid]  = b_in[tid];
    if (tid < NC) bcS[tid] = b_c[tid];
    __syncthreads();

    // ---- h = x @ W_in + b_in ----
    gemm128<false>(uS, wS, vS, hS, tid);

    const float invf[KTERMS] = {1.f, 1.f, 0.5f, 1.f/6.f, 1.f/24.f, 1.f/120.f,
                                1.f/720.f, 1.f/5040.f, 1.f/40320.f,
                                1.f/362880.f, 1.f/3628800.f};

    for (int l = 0; l < NATT; ++l) {
        __syncthreads();   // hS stores visible; previous wS consumers done
        // stage layer weights
        const float* Wl = W_att + (size_t)l * H * H;
        for (int it = tid; it < H * H / 4; it += TB) {
            float4 v = reinterpret_cast<const float4*>(Wl)[it];
            *reinterpret_cast<float4*>(&wS[it * 4]) = v;
        }
        if (tid < H) {
            vS[tid]  = b_att[l * H + tid];
            gS[tid]  = gamma[l * H + tid];
            btS[tid] = beta[l * H + tid];
        }
        __syncthreads();

        // ---- u = tanh(h @ W + b) ----
        gemm128<true>(hS, wS, vS, uS, tid);
        __syncthreads();

        // ---- attention via Taylor moments + residual + layernorm ----
        // exp(u_i*u_j) = sum_k (u_i^k)(u_j^k)/k!  (|u|<1, K=10 -> err ~7e-8)
        {
            const int row  = tid >> 1;
            const int half = tid & 1;
            float* uRow       = &uS[row * LD + half * 64];
            const float* hRow = &hS[row * LD + half * 64];

            float z[KTERMS], m[KTERMS];
            #pragma unroll
            for (int k = 0; k < KTERMS; k++) { z[k] = 0.f; m[k] = 0.f; }

            #pragma unroll 8
            for (int j = 0; j < 64; j++) {
                const float uj = uRow[j];
                const float hj = hRow[j];
                float p = uj;
                m[0] += hj;
                z[1] += p; m[1] += p * hj;
                #pragma unroll
                for (int k = 2; k < KTERMS; k++) {
                    p *= uj;
                    z[k] += p;
                    m[k] += p * hj;
                }
            }
            z[0] = 64.f;

            #pragma unroll
            for (int k = 0; k < KTERMS; k++) {
                z[k] += __shfl_xor_sync(0xffffffffu, z[k], 1);
                m[k] += __shfl_xor_sync(0xffffffffu, m[k], 1);
                z[k] *= invf[k];
                m[k] *= invf[k];
            }

            float sum = 0.f, sumsq = 0.f;
            #pragma unroll 4
            for (int i = 0; i < 64; i++) {
                const float ui = uRow[i];
                float s = z[KTERMS - 1], t = m[KTERMS - 1];
                #pragma unroll
                for (int k = KTERMS - 2; k >= 0; --k) {
                    s = fmaf(s, ui, z[k]);
                    t = fmaf(t, ui, m[k]);
                }
                const float yi = hRow[i] + __fdividef(t, s);
                sum   += yi;
                sumsq += yi * yi;
                uRow[i] = yi;          // u dead; stash y here
            }
            sum   += __shfl_xor_sync(0xffffffffu, sum, 1);
            sumsq += __shfl_xor_sync(0xffffffffu, sumsq, 1);
            const float mean = sum * (1.f / H);
            const float var  = fmaf(sumsq, 1.f / H, -mean * mean);
            const float rinv = rsqrtf(var + EPS);

            float* hW = &hS[row * LD + half * 64];
            #pragma unroll 4
            for (int i = 0; i < 64; i++) {
                const int c = half * 64 + i;
                hW[i] = (uRow[i] - mean) * rinv * gS[c] + btS[c];
            }
        }
    }
    __syncthreads();

    // ---- logits = h @ W_c + b_c ----
    {
        const int row  = tid >> 1;
        const int half = tid & 1;
        const float* hRow = &hS[row * LD + half * 64];
        float acc[NC];
        #pragma unroll
        for (int c = 0; c < NC; c++) acc[c] = 0.f;
        #pragma unroll 4
        for (int j = 0; j < 64; j++) {
            const float hj = hRow[j];
            const float* wr = &wcS[(half * 64 + j) * NC];
            #pragma unroll
            for (int c = 0; c < NC; c++) acc[c] = fmaf(hj, wr[c], acc[c]);
        }
        #pragma unroll
        for (int c = 0; c < NC; c++)
            acc[c] += __shfl_xor_sync(0xffffffffu, acc[c], 1);
        if (half == 0) {
            float* o = out + (size_t)(row0 + row) * NC;
            #pragma unroll
            for (int c = 0; c < NC; c++) o[c] = acc[c] + bcS[c];
        }
    }
}

extern "C" void kernel_launch(void* const* d_in, const int* in_sizes, int n_in,
                              void* d_out, int out_size)
{
    (void)in_sizes; (void)n_in; (void)out_size;
    const float* x     = (const float*)d_in[0];
    const float* W_in  = (const float*)d_in[1];
    const float* b_in  = (const float*)d_in[2];
    const float* W_att = (const float*)d_in[3];
    const float* b_att = (const float*)d_in[4];
    const float* gamma = (const float*)d_in[5];
    const float* beta  = (const float*)d_in[6];
    const float* W_c   = (const float*)d_in[7];
    const float* b_c   = (const float*)d_in[8];
    float* out = (float*)d_out;

    cudaFuncSetAttribute(fused_attn_kernel,
                         cudaFuncAttributeMaxDynamicSharedMemorySize, SMEM_BYTES);
    fused_attn_kernel<<<BATCH / ROWS, TB, SMEM_BYTES>>>(
        x, W_in, b_in, W_att, b_att, gamma, beta, W_c, b_c, out);
}

// round 7
// speedup vs baseline: 1.4489x; 1.4489x over previous
#include <cuda_runtime.h>
#include <cuda_bf16.h>
#include <cstdint>
#include <cstddef>

#define TB    256
#define HD    128
#define NC    10
#define KT    9            // Taylor terms k=0..8, trunc err ~7.5e-6
#define EPS   1e-5f
#define LDT   272          // tile row stride in BYTES (136 bf16) — conflict-free ldmatrix

// ---- smem byte offsets ----
#define SM_AHI  0
#define SM_ALO  (SM_AHI + 128*LDT)        // lo tile always at hi + 128*LDT
#define SM_WHI  (SM_ALO + 128*LDT)
#define SM_WLO  (SM_WHI + 128*LDT)
#define SM_SCR  (SM_WLO + 128*LDT)        // 128 rows * 37 floats (moments / classifier)
#define SM_LN   (SM_SCR + 128*37*4)       // 128 rows * 4 floats
#define SM_WC   (SM_LN  + 128*4*4)        // 1280 floats
#define SM_VEC  (SM_WC  + 1280*4)         // vS[128], gS[128], btS[128], bcS[16], pad
#define SM_TOTAL (SM_VEC + 416*4)

#define LDSM4(r, addr) \
    asm volatile("ldmatrix.sync.aligned.m8n8.x4.shared.b16 {%0,%1,%2,%3}, [%4];" \
        : "=r"((r)[0]), "=r"((r)[1]), "=r"((r)[2]), "=r"((r)[3]) : "r"(addr))

#define MMA16816(c, a, b) \
    asm volatile("mma.sync.aligned.m16n8k16.row.col.f32.bf16.bf16.f32 " \
        "{%0,%1,%2,%3},{%4,%5,%6,%7},{%8,%9},{%0,%1,%2,%3};" \
        : "+f"((c)[0]), "+f"((c)[1]), "+f"((c)[2]), "+f"((c)[3]) \
        : "r"((a)[0]), "r"((a)[1]), "r"((a)[2]), "r"((a)[3]), "r"((b)[0]), "r"((b)[1]))

// accumulator D layout (m16n8): c0,c1 = row g, cols t*2,t*2+1 ; c2,c3 = row g+8
#define ACCV(s, i) acc[(s) >> 1][(i) >> 1][((((s) & 1)) << 1) | ((i) & 1)]

__device__ __forceinline__ uint32_t smem_u32(const void* p) {
    uint32_t a;
    asm("{ .reg .u64 t; cvta.to.shared.u64 t, %1; cvt.u32.u64 %0, t; }" : "=r"(a) : "l"(p));
    return a;
}

// split fp32 pair -> bf16 hi pair + bf16 lo pair; store 4B each to hi tile and hi+128*LDT
__device__ __forceinline__ void split_store2(char* hi_base, uint32_t off, float v0, float v1) {
    __nv_bfloat16 h0 = __float2bfloat16(v0);
    __nv_bfloat16 h1 = __float2bfloat16(v1);
    float r0 = v0 - __bfloat162float(h0);
    float r1 = v1 - __bfloat162float(h1);
    __nv_bfloat162 hp; hp.x = h0; hp.y = h1;
    __nv_bfloat162 lp; lp.x = __float2bfloat16(r0); lp.y = __float2bfloat16(r1);
    *reinterpret_cast<__nv_bfloat162*>(hi_base + off)             = hp;
    *reinterpret_cast<__nv_bfloat162*>(hi_base + off + 128 * LDT) = lp;
}

__global__ __launch_bounds__(TB, 1)
void fused_attn_hmma(const float* __restrict__ x,
                     const float* __restrict__ W_in,
                     const float* __restrict__ b_in,
                     const float* __restrict__ W_att,
                     const float* __restrict__ b_att,
                     const float* __restrict__ gamma,
                     const float* __restrict__ beta,
                     const float* __restrict__ W_c,
                     const float* __restrict__ b_c,
                     float* __restrict__ out)
{
    extern __shared__ char sm[];
    float* scr   = (float*)(sm + SM_SCR);
    float* lnscr = (float*)(sm + SM_LN);
    float* wcS   = (float*)(sm + SM_WC);
    float* vS    = (float*)(sm + SM_VEC);
    float* gS    = vS + 128;
    float* btS   = vS + 256;
    float* bcS   = vS + 384;

    const int tid  = threadIdx.x;
    const int w    = tid >> 5;
    const int lane = tid & 31;
    const int quad = lane >> 2;
    const int qt   = lane & 3;
    const int rw   = (w & 3) * 32;       // warp row strip
    const int cwS  = (w >> 2) * 64;      // warp col strip
    const int strip = w >> 2;            // 0 or 1
    const int row0 = blockIdx.x * 128;

    const uint32_t smb = smem_u32(sm);
    // ldmatrix lane address offsets (relative; add tile base)
    const uint32_t aOff = smb + (uint32_t)((rw + (lane & 15)) * LDT + (lane >> 4) * 16);
    const int bRow = (lane & 7) + ((lane >> 4) & 1) * 8;
    const int bK   = ((lane >> 3) & 1) * 8;
    const uint32_t bOff = smb + (uint32_t)((cwS + bRow) * LDT + bK * 2);

    // ---- stage x -> A tiles (bf16 hi/lo) ----
    for (int i = tid; i < 128 * 64; i += TB) {
        const int r = i >> 6, c2 = (i & 63) * 2;
        const float2 v = *(const float2*)(x + (size_t)(row0 + r) * HD + c2);
        split_store2(sm + SM_AHI, (uint32_t)(r * LDT + c2 * 2), v.x, v.y);
    }
    // ---- stage W_in^T -> W tiles: tile[n][k] = W[k][n] ----
    {
        const int n = tid & 127, kh = tid >> 7;
        const float* col = W_in + n;
        #pragma unroll 4
        for (int kk = 0; kk < 32; kk++) {
            const int k = kh * 64 + kk * 2;
            const float v0 = col[(size_t)k * HD];
            const float v1 = col[(size_t)(k + 1) * HD];
            split_store2(sm + SM_WHI, (uint32_t)(n * LDT + k * 2), v0, v1);
        }
    }
    for (int i = tid; i < HD * NC; i += TB) wcS[i] = W_c[i];
    if (tid < 128) vS[tid] = b_in[tid];
    if (tid < 16)  bcS[tid] = (tid < NC) ? b_c[tid] : 0.f;
    __syncthreads();

    const float invf[KT] = {1.f, 1.f, 0.5f, 1.f/6.f, 1.f/24.f, 1.f/120.f,
                            1.f/720.f, 1.f/5040.f, 1.f/40320.f};

    float acc[2][8][4];
    float h[64];

    // triple-product split-precision GEMM into fp32 accum
    auto gemm3 = [&]() {
        #pragma unroll
        for (int rt = 0; rt < 2; rt++)
            #pragma unroll
            for (int nt = 0; nt < 8; nt++)
                #pragma unroll
                for (int c = 0; c < 4; c++) acc[rt][nt][c] = 0.f;
        const uint32_t abases[3] = {SM_AHI, SM_AHI, SM_ALO};
        const uint32_t bbases[3] = {SM_WHI, SM_WLO, SM_WHI};
        #pragma unroll
        for (int p = 0; p < 3; p++) {
            #pragma unroll
            for (int kst = 0; kst < 8; kst++) {
                const uint32_t kb = kst * 32;
                uint32_t a0[4], a1[4];
                LDSM4(a0, aOff + abases[p] + kb);
                LDSM4(a1, aOff + abases[p] + 16 * LDT + kb);
                uint32_t bfr[8][2];
                #pragma unroll
                for (int q = 0; q < 4; q++) {
                    uint32_t t4[4];
                    LDSM4(t4, bOff + bbases[p] + q * 16 * LDT + kb);
                    bfr[2*q][0]   = t4[0]; bfr[2*q][1]   = t4[1];
                    bfr[2*q+1][0] = t4[2]; bfr[2*q+1][1] = t4[3];
                }
                #pragma unroll
                for (int nt = 0; nt < 8; nt++) {
                    MMA16816(acc[0][nt], a0, bfr[nt]);
                    MMA16816(acc[1][nt], a1, bfr[nt]);
                }
            }
        }
    };

    auto writeH = [&]() {
        #pragma unroll
        for (int s = 0; s < 4; s++) {
            const int row = rw + (s >> 1) * 16 + (s & 1) * 8 + quad;
            #pragma unroll
            for (int ip = 0; ip < 8; ip++) {
                const int col = cwS + ip * 8 + qt * 2;
                split_store2(sm + SM_AHI, (uint32_t)(row * LDT + col * 2),
                             h[s * 16 + 2 * ip], h[s * 16 + 2 * ip + 1]);
            }
        }
    };

    auto stageW = [&](const float* Wg) {
        const int n = tid & 127, kh = tid >> 7;
        const float* col = Wg + n;
        #pragma unroll 4
        for (int kk = 0; kk < 32; kk++) {
            const int k = kh * 64 + kk * 2;
            const float v0 = col[(size_t)k * HD];
            const float v1 = col[(size_t)(k + 1) * HD];
            split_store2(sm + SM_WHI, (uint32_t)(n * LDT + k * 2), v0, v1);
        }
    };

    // ---- round 0: h = x @ W_in + b_in ----
    gemm3();
    {
        float bias_r[16];
        #pragma unroll
        for (int i = 0; i < 16; i++) bias_r[i] = vS[cwS + (i >> 1) * 8 + qt * 2 + (i & 1)];
        #pragma unroll
        for (int s = 0; s < 4; s++)
            #pragma unroll
            for (int i = 0; i < 16; i++) h[s * 16 + i] = ACCV(s, i) + bias_r[i];
    }
    __syncthreads();          // all ldmatrix reads of A/W done
    writeH();
    stageW(W_att);
    if (tid < 128) { vS[tid] = b_att[tid]; gS[tid] = gamma[tid]; btS[tid] = beta[tid]; }
    __syncthreads();

    // ---- 3 attention layers ----
    for (int l = 0; l < 3; ++l) {
        gemm3();

        // u = tanh(pre + bias), overwrite acc
        {
            float bias_r[16];
            #pragma unroll
            for (int i = 0; i < 16; i++) bias_r[i] = vS[cwS + (i >> 1) * 8 + qt * 2 + (i & 1)];
            #pragma unroll
            for (int s = 0; s < 4; s++)
                #pragma unroll
                for (int i = 0; i < 16; i++)
                    ACCV(s, i) = tanhf(ACCV(s, i) + bias_r[i]);
        }

        // Taylor-moment partials per row slot; quad-reduce; write strip moments
        #pragma unroll
        for (int s = 0; s < 4; s++) {
            float z[KT], m[KT];
            #pragma unroll
            for (int k = 0; k < KT; k++) { z[k] = 0.f; m[k] = 0.f; }
            z[0] = 16.f;
            #pragma unroll
            for (int i = 0; i < 16; i++) {
                const float uj = ACCV(s, i);
                const float hj = h[s * 16 + i];
                float p = uj;
                m[0] += hj;
                z[1] += p; m[1] += p * hj;
                #pragma unroll
                for (int k = 2; k < KT; k++) { p *= uj; z[k] += p; m[k] += p * hj; }
            }
            #pragma unroll
            for (int k = 0; k < KT; k++) {
                z[k] += __shfl_xor_sync(0xffffffffu, z[k], 1);
                z[k] += __shfl_xor_sync(0xffffffffu, z[k], 2);
                m[k] += __shfl_xor_sync(0xffffffffu, m[k], 1);
                m[k] += __shfl_xor_sync(0xffffffffu, m[k], 2);
            }
            const int row = rw + (s >> 1) * 16 + (s & 1) * 8 + quad;
            float* p = scr + row * 37 + strip * 18;
            #pragma unroll
            for (int k = 0; k < KT; k++)
                if ((k & 3) == qt) { p[k] = z[k]; p[KT + k] = m[k]; }
        }
        __syncthreads();

        // combine strips, eval softmax-free output, residual, LN partials
        #pragma unroll
        for (int s = 0; s < 4; s++) {
            const int row = rw + (s >> 1) * 16 + (s & 1) * 8 + quad;
            const float* p = scr + row * 37;
            float zc[KT], mc[KT];
            #pragma unroll
            for (int k = 0; k < KT; k++) {
                zc[k] = (p[k]      + p[18 + k])      * invf[k];
                mc[k] = (p[KT + k] + p[18 + KT + k]) * invf[k];
            }
            float s1 = 0.f, s2 = 0.f;
            #pragma unroll
            for (int i = 0; i < 16; i++) {
                const float ui = ACCV(s, i);
                float sd = zc[KT - 1], td = mc[KT - 1];
                #pragma unroll
                for (int k = KT - 2; k >= 0; --k) {
                    sd = fmaf(sd, ui, zc[k]);
                    td = fmaf(td, ui, mc[k]);
                }
                const float y = h[s * 16 + i] + __fdividef(td, sd);
                s1 += y; s2 += y * y;
                ACCV(s, i) = y;
            }
            s1 += __shfl_xor_sync(0xffffffffu, s1, 1);
            s1 += __shfl_xor_sync(0xffffffffu, s1, 2);
            s2 += __shfl_xor_sync(0xffffffffu, s2, 1);
            s2 += __shfl_xor_sync(0xffffffffu, s2, 2);
            if (qt == 0) {
                lnscr[row * 4 + strip * 2]     = s1;
                lnscr[row * 4 + strip * 2 + 1] = s2;
            }
        }
        __syncthreads();

        // layernorm finalize -> new h
        {
            float g_r[16], bt_r[16];
            #pragma unroll
            for (int i = 0; i < 16; i++) {
                const int c = cwS + (i >> 1) * 8 + qt * 2 + (i & 1);
                g_r[i] = gS[c]; bt_r[i] = btS[c];
            }
            #pragma unroll
            for (int s = 0; s < 4; s++) {
                const int row = rw + (s >> 1) * 16 + (s & 1) * 8 + quad;
                const float su = lnscr[row * 4]     + lnscr[row * 4 + 2];
                const float ss = lnscr[row * 4 + 1] + lnscr[row * 4 + 3];
                const float mean = su * (1.f / HD);
                const float var  = fmaf(ss, 1.f / HD, -mean * mean);
                const float rinv = rsqrtf(var + EPS);
                #pragma unroll
                for (int i = 0; i < 16; i++)
                    h[s * 16 + i] = (ACCV(s, i) - mean) * rinv * g_r[i] + bt_r[i];
            }
        }

        if (l < 2) {
            __syncthreads();          // old vS/gS reads + A ldmatrix done
            writeH();
            stageW(W_att + (size_t)(l + 1) * HD * HD);
            if (tid < 128) {
                vS[tid]  = b_att[(l + 1) * HD + tid];
                gS[tid]  = gamma[(l + 1) * HD + tid];
                btS[tid] = beta[(l + 1) * HD + tid];
            }
            __syncthreads();
        }
    }

    // ---- classifier: logits = h @ W_c + b_c ----
    #pragma unroll
    for (int s = 0; s < 4; s++) {
        float ac[NC];
        #pragma unroll
        for (int c = 0; c < NC; c++) ac[c] = 0.f;
        #pragma unroll
        for (int i = 0; i < 16; i++) {
            const float hv = h[s * 16 + i];
            const float* wr = wcS + (cwS + (i >> 1) * 8 + qt * 2 + (i & 1)) * NC;
            #pragma unroll
            for (int c = 0; c < NC; c++) ac[c] = fmaf(hv, wr[c], ac[c]);
        }
        #pragma unroll
        for (int c = 0; c < NC; c++) {
            ac[c] += __shfl_xor_sync(0xffffffffu, ac[c], 1);
            ac[c] += __shfl_xor_sync(0xffffffffu, ac[c], 2);
        }
        const int row = rw + (s >> 1) * 16 + (s & 1) * 8 + quad;
        #pragma unroll
        for (int c = 0; c < NC; c++)
            if ((c & 3) == qt) scr[row * 37 + strip * 10 + c] = ac[c];
    }
    __syncthreads();
    if (tid < 128) {
        const float* p = scr + tid * 37;
        float* o = out + (size_t)(row0 + tid) * NC;
        #pragma unroll
        for (int c = 0; c < NC; c++) o[c] = p[c] + p[10 + c] + bcS[c];
    }
}

extern "C" void kernel_launch(void* const* d_in, const int* in_sizes, int n_in,
                              void* d_out, int out_size)
{
    (void)in_sizes; (void)n_in; (void)out_size;
    const float* x     = (const float*)d_in[0];
    const float* W_in  = (const float*)d_in[1];
    const float* b_in  = (const float*)d_in[2];
    const float* W_att = (const float*)d_in[3];
    const float* b_att = (const float*)d_in[4];
    const float* gamma = (const float*)d_in[5];
    const float* beta  = (const float*)d_in[6];
    const float* W_c   = (const float*)d_in[7];
    const float* b_c   = (const float*)d_in[8];
    float* out = (float*)d_out;

    cudaFuncSetAttribute(fused_attn_hmma,
                         cudaFuncAttributeMaxDynamicSharedMemorySize, SM_TOTAL);
    fused_attn_hmma<<<16384 / 128, TB, SM_TOTAL>>>(
        x, W_in, b_in, W_att, b_att, gamma, beta, W_c, b_c, out);
}

// round 8
// speedup vs baseline: 1.4831x; 1.0237x over previous
#include <cuda_runtime.h>
#include <cuda_bf16.h>
#include <cstdint>
#include <cstddef>

#define TB    512
#define HD    128
#define NC    10
#define KT    9            // Taylor terms k=0..8, trunc err ~7.5e-6
#define EPS   1e-5f
#define LDT   272          // tile row stride in BYTES (136 bf16) — conflict-free ldmatrix

// ---- smem byte offsets ----
#define SM_AHI  0
#define SM_ALO  (SM_AHI + 128*LDT)        // lo tile always at hi + 128*LDT
#define SM_WHI  (SM_ALO + 128*LDT)
#define SM_WLO  (SM_WHI + 128*LDT)
#define SM_SCR  (SM_WLO + 128*LDT)        // 128 rows * 37 floats (moments / classifier)
#define SM_LN   (SM_SCR + 128*37*4)       // 128 rows * 4 floats
#define SM_WC   (SM_LN  + 128*4*4)        // 1280 floats
#define SM_VEC  (SM_WC  + 1280*4)         // vS[128], gS[128], btS[128], bcS[16], pad
#define SM_TOTAL (SM_VEC + 416*4)

#define LDSM4(r, addr) \
    asm volatile("ldmatrix.sync.aligned.m8n8.x4.shared.b16 {%0,%1,%2,%3}, [%4];" \
        : "=r"((r)[0]), "=r"((r)[1]), "=r"((r)[2]), "=r"((r)[3]) : "r"(addr))

#define MMA16816(c, a, b) \
    asm volatile("mma.sync.aligned.m16n8k16.row.col.f32.bf16.bf16.f32 " \
        "{%0,%1,%2,%3},{%4,%5,%6,%7},{%8,%9},{%0,%1,%2,%3};" \
        : "+f"((c)[0]), "+f"((c)[1]), "+f"((c)[2]), "+f"((c)[3]) \
        : "r"((a)[0]), "r"((a)[1]), "r"((a)[2]), "r"((a)[3]), "r"((b)[0]), "r"((b)[1]))

// accumulator D layout (m16n8): c0,c1 = row quad, cols qt*2+{0,1}; c2,c3 = row quad+8
// slot s in {0,1}: s=0 -> row rw+quad (c0,c1), s=1 -> row rw+8+quad (c2,c3)
#define ACCV(s, i) acc[(i) >> 1][(((s) & 1) << 1) | ((i) & 1)]

__device__ __forceinline__ uint32_t smem_u32(const void* p) {
    uint32_t a;
    asm("{ .reg .u64 t; cvta.to.shared.u64 t, %1; cvt.u32.u64 %0, t; }" : "=r"(a) : "l"(p));
    return a;
}
__device__ __forceinline__ float fast_tanh(float v) {
    float r;
    asm("tanh.approx.f32 %0, %1;" : "=f"(r) : "f"(v));
    return r;
}

// split fp32 pair -> bf16 hi pair + bf16 lo pair; store 4B each to hi tile and hi+128*LDT
__device__ __forceinline__ void split_store2(char* hi_base, uint32_t off, float v0, float v1) {
    __nv_bfloat16 h0 = __float2bfloat16(v0);
    __nv_bfloat16 h1 = __float2bfloat16(v1);
    float r0 = v0 - __bfloat162float(h0);
    float r1 = v1 - __bfloat162float(h1);
    __nv_bfloat162 hp; hp.x = h0; hp.y = h1;
    __nv_bfloat162 lp; lp.x = __float2bfloat16(r0); lp.y = __float2bfloat16(r1);
    *reinterpret_cast<__nv_bfloat162*>(hi_base + off)             = hp;
    *reinterpret_cast<__nv_bfloat162*>(hi_base + off + 128 * LDT) = lp;
}

__global__ __launch_bounds__(TB, 1)
void fused_attn_hmma(const float* __restrict__ x,
                     const float* __restrict__ W_in,
                     const float* __restrict__ b_in,
                     const float* __restrict__ W_att,
                     const float* __restrict__ b_att,
                     const float* __restrict__ gamma,
                     const float* __restrict__ beta,
                     const float* __restrict__ W_c,
                     const float* __restrict__ b_c,
                     float* __restrict__ out)
{
    extern __shared__ char sm[];
    float* scr   = (float*)(sm + SM_SCR);
    float* lnscr = (float*)(sm + SM_LN);
    float* wcS   = (float*)(sm + SM_WC);
    float* vS    = (float*)(sm + SM_VEC);
    float* gS    = vS + 128;
    float* btS   = vS + 256;
    float* bcS   = vS + 384;

    const int tid  = threadIdx.x;
    const int w    = tid >> 5;
    const int lane = tid & 31;
    const int quad = lane >> 2;
    const int qt   = lane & 3;
    const int rw   = (w & 7) * 16;       // warp row strip (16 rows)
    const int strip = w >> 3;            // 0 or 1
    const int cwS  = strip * 64;         // warp col strip (64 cols)
    const int row0 = blockIdx.x * 128;

    const uint32_t smb = smem_u32(sm);
    // ldmatrix lane address offsets (relative; add tile base)
    const uint32_t aOff = smb + (uint32_t)((rw + (lane & 15)) * LDT + (lane >> 4) * 16);
    const int bRow = (lane & 7) + ((lane >> 4) & 1) * 8;
    const int bK   = ((lane >> 3) & 1) * 8;
    const uint32_t bOff = smb + (uint32_t)((cwS + bRow) * LDT + bK * 2);

    // ---- stage x -> A tiles (bf16 hi/lo) ----
    for (int i = tid; i < 128 * 64; i += TB) {
        const int r = i >> 6, c2 = (i & 63) * 2;
        const float2 v = *(const float2*)(x + (size_t)(row0 + r) * HD + c2);
        split_store2(sm + SM_AHI, (uint32_t)(r * LDT + c2 * 2), v.x, v.y);
    }
    // ---- stage W_in^T -> W tiles: tile[n][k] = W[k][n] ----
    {
        const int n = tid & 127, kh = tid >> 7;   // kh in 0..3, 32 k-values each
        const float* col = W_in + n;
        #pragma unroll 4
        for (int kk = 0; kk < 16; kk++) {
            const int k = kh * 32 + kk * 2;
            const float v0 = col[(size_t)k * HD];
            const float v1 = col[(size_t)(k + 1) * HD];
            split_store2(sm + SM_WHI, (uint32_t)(n * LDT + k * 2), v0, v1);
        }
    }
    for (int i = tid; i < HD * NC; i += TB) wcS[i] = W_c[i];
    if (tid < 128) vS[tid] = b_in[tid];
    if (tid < 16)  bcS[tid] = (tid < NC) ? b_c[tid] : 0.f;
    __syncthreads();

    const float invf[KT] = {1.f, 1.f, 0.5f, 1.f/6.f, 1.f/24.f, 1.f/120.f,
                            1.f/720.f, 1.f/5040.f, 1.f/40320.f};

    float acc[8][4];
    float h[32];

    // triple-product split-precision GEMM into fp32 accum (warp tile 16x64)
    auto gemm3 = [&]() {
        #pragma unroll
        for (int nt = 0; nt < 8; nt++)
            #pragma unroll
            for (int c = 0; c < 4; c++) acc[nt][c] = 0.f;
        const uint32_t abases[3] = {SM_AHI, SM_AHI, SM_ALO};
        const uint32_t bbases[3] = {SM_WHI, SM_WLO, SM_WHI};
        #pragma unroll
        for (int p = 0; p < 3; p++) {
            #pragma unroll
            for (int kst = 0; kst < 8; kst++) {
                const uint32_t kb = kst * 32;
                uint32_t a0[4];
                LDSM4(a0, aOff + abases[p] + kb);
                uint32_t bfr[8][2];
                #pragma unroll
                for (int q = 0; q < 4; q++) {
                    uint32_t t4[4];
                    LDSM4(t4, bOff + bbases[p] + q * 16 * LDT + kb);
                    bfr[2*q][0]   = t4[0]; bfr[2*q][1]   = t4[1];
                    bfr[2*q+1][0] = t4[2]; bfr[2*q+1][1] = t4[3];
                }
                #pragma unroll
                for (int nt = 0; nt < 8; nt++)
                    MMA16816(acc[nt], a0, bfr[nt]);
            }
        }
    };

    auto writeH = [&]() {
        #pragma unroll
        for (int s = 0; s < 2; s++) {
            const int row = rw + s * 8 + quad;
            #pragma unroll
            for (int ip = 0; ip < 8; ip++) {
                const int col = cwS + ip * 8 + qt * 2;
                split_store2(sm + SM_AHI, (uint32_t)(row * LDT + col * 2),
                             h[s * 16 + 2 * ip], h[s * 16 + 2 * ip + 1]);
            }
        }
    };

    auto stageW = [&](const float* Wg) {
        const int n = tid & 127, kh = tid >> 7;
        const float* col = Wg + n;
        #pragma unroll 4
        for (int kk = 0; kk < 16; kk++) {
            const int k = kh * 32 + kk * 2;
            const float v0 = col[(size_t)k * HD];
            const float v1 = col[(size_t)(k + 1) * HD];
            split_store2(sm + SM_WHI, (uint32_t)(n * LDT + k * 2), v0, v1);
        }
    };

    // ---- round 0: h = x @ W_in + b_in ----
    gemm3();
    {
        float bias_r[16];
        #pragma unroll
        for (int i = 0; i < 16; i++) bias_r[i] = vS[cwS + (i >> 1) * 8 + qt * 2 + (i & 1)];
        #pragma unroll
        for (int s = 0; s < 2; s++)
            #pragma unroll
            for (int i = 0; i < 16; i++) h[s * 16 + i] = ACCV(s, i) + bias_r[i];
    }
    __syncthreads();          // all ldmatrix reads of A/W done
    writeH();
    stageW(W_att);
    if (tid < 128) { vS[tid] = b_att[tid]; gS[tid] = gamma[tid]; btS[tid] = beta[tid]; }
    __syncthreads();

    // ---- 3 attention layers ----
    for (int l = 0; l < 3; ++l) {
        gemm3();

        // u = tanh(pre + bias), overwrite acc
        {
            float bias_r[16];
            #pragma unroll
            for (int i = 0; i < 16; i++) bias_r[i] = vS[cwS + (i >> 1) * 8 + qt * 2 + (i & 1)];
            #pragma unroll
            for (int s = 0; s < 2; s++)
                #pragma unroll
                for (int i = 0; i < 16; i++)
                    ACCV(s, i) = fast_tanh(ACCV(s, i) + bias_r[i]);
        }

        // Taylor-moment partials per row slot; quad-reduce; write strip moments
        #pragma unroll
        for (int s = 0; s < 2; s++) {
            float z[KT], m[KT];
            #pragma unroll
            for (int k = 0; k < KT; k++) { z[k] = 0.f; m[k] = 0.f; }
            z[0] = 16.f;
            #pragma unroll
            for (int i = 0; i < 16; i++) {
                const float uj = ACCV(s, i);
                const float hj = h[s * 16 + i];
                float p = uj;
                m[0] += hj;
                z[1] += p; m[1] += p * hj;
                #pragma unroll
                for (int k = 2; k < KT; k++) { p *= uj; z[k] += p; m[k] += p * hj; }
            }
            #pragma unroll
            for (int k = 0; k < KT; k++) {
                z[k] += __shfl_xor_sync(0xffffffffu, z[k], 1);
                z[k] += __shfl_xor_sync(0xffffffffu, z[k], 2);
                m[k] += __shfl_xor_sync(0xffffffffu, m[k], 1);
                m[k] += __shfl_xor_sync(0xffffffffu, m[k], 2);
            }
            const int row = rw + s * 8 + quad;
            float* p = scr + row * 37 + strip * 18;
            #pragma unroll
            for (int k = 0; k < KT; k++)
                if ((k & 3) == qt) { p[k] = z[k]; p[KT + k] = m[k]; }
        }
        __syncthreads();

        // combine strips, eval softmax-free output, residual, LN partials
        #pragma unroll
        for (int s = 0; s < 2; s++) {
            const int row = rw + s * 8 + quad;
            const float* p = scr + row * 37;
            float zc[KT], mc[KT];
            #pragma unroll
            for (int k = 0; k < KT; k++) {
                zc[k] = (p[k]      + p[18 + k])      * invf[k];
                mc[k] = (p[KT + k] + p[18 + KT + k]) * invf[k];
            }
            float s1 = 0.f, s2 = 0.f;
            #pragma unroll
            for (int i = 0; i < 16; i++) {
                const float ui = ACCV(s, i);
                float sd = zc[KT - 1], td = mc[KT - 1];
                #pragma unroll
                for (int k = KT - 2; k >= 0; --k) {
                    sd = fmaf(sd, ui, zc[k]);
                    td = fmaf(td, ui, mc[k]);
                }
                const float y = h[s * 16 + i] + __fdividef(td, sd);
                s1 += y; s2 += y * y;
                ACCV(s, i) = y;
            }
            s1 += __shfl_xor_sync(0xffffffffu, s1, 1);
            s1 += __shfl_xor_sync(0xffffffffu, s1, 2);
            s2 += __shfl_xor_sync(0xffffffffu, s2, 1);
            s2 += __shfl_xor_sync(0xffffffffu, s2, 2);
            if (qt == 0) {
                lnscr[row * 4 + strip * 2]     = s1;
                lnscr[row * 4 + strip * 2 + 1] = s2;
            }
        }
        __syncthreads();

        // layernorm finalize -> new h
        {
            float g_r[16], bt_r[16];
            #pragma unroll
            for (int i = 0; i < 16; i++) {
                const int c = cwS + (i >> 1) * 8 + qt * 2 + (i & 1);
                g_r[i] = gS[c]; bt_r[i] = btS[c];
            }
            #pragma unroll
            for (int s = 0; s < 2; s++) {
                const int row = rw + s * 8 + quad;
                const float su = lnscr[row * 4]     + lnscr[row * 4 + 2];
                const float ss = lnscr[row * 4 + 1] + lnscr[row * 4 + 3];
                const float mean = su * (1.f / HD);
                const float var  = fmaf(ss, 1.f / HD, -mean * mean);
                const float rinv = rsqrtf(var + EPS);
                #pragma unroll
                for (int i = 0; i < 16; i++)
                    h[s * 16 + i] = (ACCV(s, i) - mean) * rinv * g_r[i] + bt_r[i];
            }
        }

        if (l < 2) {
            __syncthreads();          // old vS/gS reads + A ldmatrix done
            writeH();
            stageW(W_att + (size_t)(l + 1) * HD * HD);
            if (tid < 128) {
                vS[tid]  = b_att[(l + 1) * HD + tid];
                gS[tid]  = gamma[(l + 1) * HD + tid];
                btS[tid] = beta[(l + 1) * HD + tid];
            }
            __syncthreads();
        }
    }

    // ---- classifier: logits = h @ W_c + b_c ----
    #pragma unroll
    for (int s = 0; s < 2; s++) {
        float ac[NC];
        #pragma unroll
        for (int c = 0; c < NC; c++) ac[c] = 0.f;
        #pragma unroll
        for (int i = 0; i < 16; i++) {
            const float hv = h[s * 16 + i];
            const float* wr = wcS + (cwS + (i >> 1) * 8 + qt * 2 + (i & 1)) * NC;
            #pragma unroll
            for (int c = 0; c < NC; c++) ac[c] = fmaf(hv, wr[c], ac[c]);
        }
        #pragma unroll
        for (int c = 0; c < NC; c++) {
            ac[c] += __shfl_xor_sync(0xffffffffu, ac[c], 1);
            ac[c] += __shfl_xor_sync(0xffffffffu, ac[c], 2);
        }
        const int row = rw + s * 8 + quad;
        #pragma unroll
        for (int c = 0; c < NC; c++)
            if ((c & 3) == qt) scr[row * 37 + strip * 10 + c] = ac[c];
    }
    __syncthreads();
    if (tid < 128) {
        const float* p = scr + tid * 37;
        float* o = out + (size_t)(row0 + tid) * NC;
        #pragma unroll
        for (int c = 0; c < NC; c++) o[c] = p[c] + p[10 + c] + bcS[c];
    }
}

extern "C" void kernel_launch(void* const* d_in, const int* in_sizes, int n_in,
                              void* d_out, int out_size)
{
    (void)in_sizes; (void)n_in; (void)out_size;
    const float* x     = (const float*)d_in[0];
    const float* W_in  = (const float*)d_in[1];
    const float* b_in  = (const float*)d_in[2];
    const float* W_att = (const float*)d_in[3];
    const float* b_att = (const float*)d_in[4];
    const float* gamma = (const float*)d_in[5];
    const float* beta  = (const float*)d_in[6];
    const float* W_c   = (const float*)d_in[7];
    const float* b_c   = (const float*)d_in[8];
    float* out = (float*)d_out;

    cudaFuncSetAttribute(fused_attn_hmma,
                         cudaFuncAttributeMaxDynamicSharedMemorySize, SM_TOTAL);
    fused_attn_hmma<<<16384 / 128, TB, SM_TOTAL>>>(
        x, W_in, b_in, W_att, b_att, gamma, beta, W_c, b_c, out);
}